// round 2
// baseline (speedup 1.0000x reference)
#include <cuda_runtime.h>

typedef unsigned long long u64;

#define BATCH   262144
#define DD      6
#define HH      100
#define TT      8
#define NPAIRS  (BATCH/2)
#define NELEM   (BATCH*DD)
#define NBLOCKS 148
#define NTHREADS 512
#define TOTTHR  (NBLOCKS*NTHREADS)
#define NSLOTS  72
#define MAXSTEPS 64

// ---- device scratch (no allocation allowed) ----
__device__ u64   g_y [2][DD][NPAIRS];
__device__ u64   g_fy[2][DD][NPAIRS];
__device__ float g_part[NSLOTS][NBLOCKS][2];
__device__ unsigned g_count;

__global__ void ode_init_kernel() { g_count = 0u; }

// ---- packed f32x2 helpers (sm_103a) ----
__device__ __forceinline__ u64 F2FMA(u64 a, u64 b, u64 c) {
    u64 d; asm("fma.rn.f32x2 %0,%1,%2,%3;" : "=l"(d) : "l"(a), "l"(b), "l"(c)); return d;
}
__device__ __forceinline__ u64 F2MUL(u64 a, u64 b) {
    u64 d; asm("mul.rn.f32x2 %0,%1,%2;" : "=l"(d) : "l"(a), "l"(b)); return d;
}
__device__ __forceinline__ u64 PACK2(float lo, float hi) {
    u64 d; asm("mov.b64 %0,{%1,%2};" : "=l"(d) : "f"(lo), "f"(hi)); return d;
}
__device__ __forceinline__ float2 UNPACK2(u64 v) {
    float2 r; asm("mov.b64 {%0,%1},%2;" : "=f"(r.x), "=f"(r.y) : "l"(v)); return r;
}
__device__ __forceinline__ u64 DUP(float s) { return PACK2(s, s); }
__device__ __forceinline__ float EX2A(float x){ float r; asm("ex2.approx.f32 %0,%1;":"=f"(r):"f"(x)); return r; }
__device__ __forceinline__ float RCPA(float x){ float r; asm("rcp.approx.f32 %0,%1;":"=f"(r):"f"(x)); return r; }

// tanh(x) = 1 - 2/(exp(2x)+1); rel err ~1e-6 (safe vs 1e-3 output gate)
__device__ __forceinline__ u64 TANH2(u64 a) {
    float2 x = UNPACK2(F2MUL(a, DUP(2.885390081777927f)));  // 2*log2(e)
    float e0 = EX2A(x.x), e1 = EX2A(x.y);
    float r0 = RCPA(e0 + 1.0f), r1 = RCPA(e1 + 1.0f);
    return PACK2(fmaf(-2.0f, r0, 1.0f), fmaf(-2.0f, r1, 1.0f));
}

// ---- MLP: out = tanh(yin @ W1^T + b1) @ W2^T + b2 (packed, weights in smem) ----
// sW1 rows: 8 u64 per j = [w1*6 | b1 | pad].  sW2 rows: 6 u64 per j (W2[d][j] dup'd).
__device__ __forceinline__ void mlp(const u64* __restrict__ sW1, const u64* __restrict__ sW2,
                                    const u64* __restrict__ sb2,
                                    const u64 yin[DD], u64 out[DD]) {
    u64 o0=sb2[0],o1=sb2[1],o2=sb2[2],o3=sb2[3],o4=sb2[4],o5=sb2[5];
#pragma unroll 2
    for (int j = 0; j < HH; j++) {
        const ulonglong2* r = (const ulonglong2*)(sW1 + j*8);
        ulonglong2 wa = r[0], wb = r[1], wc = r[2], wd = r[3];
        u64 a = wd.x;                                   // b1[j]
        a = F2FMA(wa.x, yin[0], a); a = F2FMA(wa.y, yin[1], a);
        a = F2FMA(wb.x, yin[2], a); a = F2FMA(wb.y, yin[3], a);
        a = F2FMA(wc.x, yin[4], a); a = F2FMA(wc.y, yin[5], a);
        u64 t = TANH2(a);
        const ulonglong2* q = (const ulonglong2*)(sW2 + j*6);
        ulonglong2 va = q[0], vb = q[1], vc = q[2];
        o0 = F2FMA(va.x, t, o0); o1 = F2FMA(va.y, t, o1);
        o2 = F2FMA(vb.x, t, o2); o3 = F2FMA(vb.y, t, o3);
        o4 = F2FMA(vc.x, t, o4); o5 = F2FMA(vc.y, t, o5);
    }
    out[0]=o0; out[1]=o1; out[2]=o2; out[3]=o3; out[4]=o4; out[5]=o5;
}

__device__ __forceinline__ void axpy(u64 t[DD], const u64 k[DD], float c) {
    u64 cc = DUP(c);
#pragma unroll
    for (int d = 0; d < DD; d++) t[d] = F2FMA(cc, k[d], t[d]);
}

// ---- deterministic grid-wide sum of two floats; slot must increase per call ----
__device__ float2 reduce2(float a, float b, int slot) {
    __shared__ float swA[NTHREADS/32], swB[NTHREADS/32];
    __shared__ float2 bc;
    unsigned lane = threadIdx.x & 31, wid = threadIdx.x >> 5;
#pragma unroll
    for (int o = 16; o; o >>= 1) {
        a += __shfl_xor_sync(0xffffffffu, a, o);
        b += __shfl_xor_sync(0xffffffffu, b, o);
    }
    if (lane == 0) { swA[wid] = a; swB[wid] = b; }
    __syncthreads();
    if (threadIdx.x == 0) {
        float sa = 0.f, sb = 0.f;
#pragma unroll
        for (int i = 0; i < NTHREADS/32; i++) { sa += swA[i]; sb += swB[i]; }
        g_part[slot][blockIdx.x][0] = sa;
        g_part[slot][blockIdx.x][1] = sb;
        __threadfence();
        atomicAdd(&g_count, 1u);
        unsigned target = (unsigned)(slot + 1) * NBLOCKS;
        while (atomicAdd(&g_count, 0u) < target) __nanosleep(64);
        __threadfence();
        float ta = 0.f, tb = 0.f;
        for (int i = 0; i < NBLOCKS; i++) {
            ta += __ldcg(&g_part[slot][i][0]);
            tb += __ldcg(&g_part[slot][i][1]);
        }
        bc = make_float2(ta, tb);
    }
    __syncthreads();
    return bc;
}

__device__ __forceinline__ void err_acc(float& acc, u64 e, u64 yv, u64 yn) {
    float2 ef = UNPACK2(e), y0 = UNPACK2(yv), y1 = UNPACK2(yn);
    float s0 = fmaf(1e-7f, fmaxf(fabsf(y0.x), fabsf(y1.x)), 1e-9f);
    float s1 = fmaf(1e-7f, fmaxf(fabsf(y0.y), fabsf(y1.y)), 1e-9f);
    float q0 = __fdividef(ef.x, s0), q1 = __fdividef(ef.y, s1);
    acc = fmaf(q0, q0, acc); acc = fmaf(q1, q1, acc);
}

__global__ void __launch_bounds__(NTHREADS, 1)
ode_kernel(const float* __restrict__ in_seq, const float* __restrict__ W1,
           const float* __restrict__ b1, const float* __restrict__ W2,
           const float* __restrict__ b2, const float* __restrict__ Wl,
           const float* __restrict__ bl, float* __restrict__ out) {
    const float A21f = 0.2f;
    const float A31f = 3.f/40.f,  A32f = 9.f/40.f;
    const float A41f = 44.f/45.f, A42f = -56.f/15.f, A43f = 32.f/9.f;
    const float A51f = 19372.f/6561.f, A52f = -25360.f/2187.f, A53f = 64448.f/6561.f, A54f = -212.f/729.f;
    const float A61f = 9017.f/3168.f,  A62f = -355.f/33.f,     A63f = 46732.f/5247.f,
                A64f = 49.f/176.f,     A65f = -5103.f/18656.f;
    const float B1f = 35.f/384.f, B3f = 500.f/1113.f, B4f = 125.f/192.f, B5f = -2187.f/6784.f, B6f = 11.f/84.f;
    const float E1f = 71.f/57600.f, E3f = -71.f/16695.f, E4f = 71.f/1920.f,
                E5f = -17253.f/339200.f, E6f = 22.f/525.f, E7f = -1.f/40.f;
    const float INVN = 1.0f / (float)NELEM;

    __shared__ __align__(16) u64 sW1[HH*8];
    __shared__ __align__(16) u64 sW2[HH*6];
    __shared__ __align__(16) u64 sb2[DD];

    const int tid  = threadIdx.x;
    const int gtid = blockIdx.x * NTHREADS + tid;

    for (int i = tid; i < HH; i += NTHREADS) {
#pragma unroll
        for (int d = 0; d < DD; d++) {
            float w1v = W1[i*DD + d];   sW1[i*8 + d] = PACK2(w1v, w1v);
            float w2v = W2[d*HH + i];   sW2[i*6 + d] = PACK2(w2v, w2v);
        }
        float bv = b1[i];
        sW1[i*8 + 6] = PACK2(bv, bv);
        sW1[i*8 + 7] = 0ull;
    }
    if (tid < DD) { float v = b2[tid]; sb2[tid] = PACK2(v, v); }
    __syncthreads();

    int slot = 0;

    // ---- Pass A: y0 = input_seq[:,-1,:], f0 = f(y0), accumulate d0,d1 ----
    float a0 = 0.f, a1 = 0.f;
    for (int p = gtid; p < NPAIRS; p += TOTTHR) {
        const float* r0 = in_seq + (size_t)(2*p) * (TT*DD) + (TT-1)*DD;
        const float* r1 = r0 + TT*DD;
        u64 y[DD], f[DD];
#pragma unroll
        for (int d = 0; d < DD; d++) y[d] = PACK2(r0[d], r1[d]);
        mlp(sW1, sW2, sb2, y, f);
#pragma unroll
        for (int d = 0; d < DD; d++) {
            g_y[0][d][p]  = y[d];
            g_fy[0][d][p] = f[d];
            float2 yv = UNPACK2(y[d]), fv = UNPACK2(f[d]);
            float s0 = fmaf(1e-7f, fabsf(yv.x), 1e-9f);
            float s1 = fmaf(1e-7f, fabsf(yv.y), 1e-9f);
            float q0 = __fdividef(yv.x, s0), q1 = __fdividef(yv.y, s1);
            a0 = fmaf(q0, q0, a0); a0 = fmaf(q1, q1, a0);
            q0 = __fdividef(fv.x, s0); q1 = __fdividef(fv.y, s1);
            a1 = fmaf(q0, q0, a1); a1 = fmaf(q1, q1, a1);
        }
    }
    float2 s01 = reduce2(a0, a1, slot++);
    float d0 = sqrtf(s01.x * INVN), d1 = sqrtf(s01.y * INVN);
    float h0 = ((d0 < 1e-5f) || (d1 < 1e-5f)) ? 1e-6f : 0.01f * d0 / fmaxf(d1, 1e-12f);

    // ---- Pass B: d2 = rms((f(y0+h0*f0)-f0)/scale)/h0 ----
    float a2 = 0.f;
    for (int p = gtid; p < NPAIRS; p += TOTTHR) {
        u64 y[DD], f[DD], y1v[DD], f1v[DD];
#pragma unroll
        for (int d = 0; d < DD; d++) { y[d] = g_y[0][d][p]; f[d] = g_fy[0][d][p]; }
        u64 hh = DUP(h0);
#pragma unroll
        for (int d = 0; d < DD; d++) y1v[d] = F2FMA(hh, f[d], y[d]);
        mlp(sW1, sW2, sb2, y1v, f1v);
#pragma unroll
        for (int d = 0; d < DD; d++) {
            float2 yv = UNPACK2(y[d]), fv = UNPACK2(f[d]), gv = UNPACK2(f1v[d]);
            float s0 = fmaf(1e-7f, fabsf(yv.x), 1e-9f);
            float s1 = fmaf(1e-7f, fabsf(yv.y), 1e-9f);
            float q0 = __fdividef(gv.x - fv.x, s0), q1 = __fdividef(gv.y - fv.y, s1);
            a2 = fmaf(q0, q0, a2); a2 = fmaf(q1, q1, a2);
        }
    }
    float2 s2 = reduce2(a2, 0.f, slot++);
    float d2 = sqrtf(s2.x * INVN) / h0;
    float dm = fmaxf(d1, d2);
    float h1 = (dm <= 1e-15f) ? fmaxf(1e-6f, h0 * 1e-3f)
                              : powf(0.01f / fmaxf(dm, 1e-15f), 0.2f);
    float h = fminf(fminf(100.f * h0, h1), 1.0f);

    // ---- adaptive step loop with early exit ----
    float t = 0.f;
    int cur = 0;
    for (int it = 0; it < MAXSTEPS; it++) {
        if (t >= 1.0f - 1e-12f) break;
        float hc = fminf(h, 1.0f - t);
        float acc = 0.f;
        for (int p = gtid; p < NPAIRS; p += TOTTHR) {
            u64 y[DD], k1[DD], k2[DD], k3[DD], k4[DD], k5[DD], k6[DD];
            u64 tmp[DD], ynew[DD], e[DD];
#pragma unroll
            for (int d = 0; d < DD; d++) { y[d] = g_y[cur][d][p]; k1[d] = g_fy[cur][d][p]; }
            // stage 2
#pragma unroll
            for (int d = 0; d < DD; d++) tmp[d] = y[d];
            axpy(tmp, k1, hc*A21f);
            mlp(sW1, sW2, sb2, tmp, k2);
            // stage 3
#pragma unroll
            for (int d = 0; d < DD; d++) tmp[d] = y[d];
            axpy(tmp, k1, hc*A31f); axpy(tmp, k2, hc*A32f);
            mlp(sW1, sW2, sb2, tmp, k3);
            // stage 4
#pragma unroll
            for (int d = 0; d < DD; d++) tmp[d] = y[d];
            axpy(tmp, k1, hc*A41f); axpy(tmp, k2, hc*A42f); axpy(tmp, k3, hc*A43f);
            mlp(sW1, sW2, sb2, tmp, k4);
            // stage 5
#pragma unroll
            for (int d = 0; d < DD; d++) tmp[d] = y[d];
            axpy(tmp, k1, hc*A51f); axpy(tmp, k2, hc*A52f); axpy(tmp, k3, hc*A53f); axpy(tmp, k4, hc*A54f);
            mlp(sW1, sW2, sb2, tmp, k5);
            // stage 6 (k2 dead after this input)
#pragma unroll
            for (int d = 0; d < DD; d++) tmp[d] = y[d];
            axpy(tmp, k1, hc*A61f); axpy(tmp, k2, hc*A62f); axpy(tmp, k3, hc*A63f);
            axpy(tmp, k4, hc*A64f); axpy(tmp, k5, hc*A65f);
            mlp(sW1, sW2, sb2, tmp, k6);
            // y_new and error combo
#pragma unroll
            for (int d = 0; d < DD; d++) ynew[d] = y[d];
            axpy(ynew, k1, hc*B1f); axpy(ynew, k3, hc*B3f); axpy(ynew, k4, hc*B4f);
            axpy(ynew, k5, hc*B5f); axpy(ynew, k6, hc*B6f);
            {
                u64 c = DUP(hc*E1f);
#pragma unroll
                for (int d = 0; d < DD; d++) e[d] = F2MUL(c, k1[d]);
            }
            axpy(e, k3, hc*E3f); axpy(e, k4, hc*E4f); axpy(e, k5, hc*E5f); axpy(e, k6, hc*E6f);
            // k7 = f(y_new); reuse k2 storage
            mlp(sW1, sW2, sb2, ynew, k2);
            axpy(e, k2, hc*E7f);
#pragma unroll
            for (int d = 0; d < DD; d++) {
                g_y [cur^1][d][p] = ynew[d];
                g_fy[cur^1][d][p] = k2[d];
                err_acc(acc, e[d], y[d], ynew[d]);
            }
        }
        float2 se = reduce2(acc, 0.f, slot++);
        float en = sqrtf(se.x * INVN);
        float pw = exp2f(-0.2f * log2f(fmaxf(en, 1e-10f)));
        float factor = fminf(fmaxf(0.9f * pw, 0.2f), 10.0f);
        if (en <= 1.0f) { t += hc; cur ^= 1; }
        h = hc * factor;
    }

    // ---- output: out[b] = dot(yT[b], Wl) + bl ----
    float wl0 = Wl[0], wl1 = Wl[1], wl2 = Wl[2], wl3 = Wl[3], wl4 = Wl[4], wl5 = Wl[5];
    float blv = bl[0];
    for (int p = gtid; p < NPAIRS; p += TOTTHR) {
        float o0 = blv, o1 = blv;
#pragma unroll
        for (int d = 0; d < DD; d++) {
            float2 yv = UNPACK2(g_y[cur][d][p]);
            float w = (d==0)?wl0:(d==1)?wl1:(d==2)?wl2:(d==3)?wl3:(d==4)?wl4:wl5;
            o0 = fmaf(yv.x, w, o0);
            o1 = fmaf(yv.y, w, o1);
        }
        out[2*p]   = o0;
        out[2*p+1] = o1;
    }
}

extern "C" void kernel_launch(void* const* d_in, const int* in_sizes, int n_in,
                              void* d_out, int out_size) {
    const float* in_seq = (const float*)d_in[0];
    const float* W1 = (const float*)d_in[1];
    const float* b1 = (const float*)d_in[2];
    const float* W2 = (const float*)d_in[3];
    const float* b2 = (const float*)d_in[4];
    const float* Wl = (const float*)d_in[5];
    const float* bl = (const float*)d_in[6];
    float* out = (float*)d_out;
    ode_init_kernel<<<1, 1>>>();
    ode_kernel<<<NBLOCKS, NTHREADS>>>(in_seq, W1, b1, W2, b2, Wl, bl, out);
}

// round 3
// speedup vs baseline: 1.2100x; 1.2100x over previous
#include <cuda_runtime.h>

typedef unsigned long long u64;

#define BATCH   262144
#define DD      6
#define HH      100
#define TT      8
#define NPAIRS  (BATCH/2)
#define NELEM   (BATCH*DD)
#define NBLOCKS 148
#define NTHREADS 512
#define TOTTHR  (NBLOCKS*NTHREADS)
#define NSLOTS  72
#define MAXSTEPS 64

// ---- device scratch (no allocation allowed) ----
__device__ u64   g_y [2][DD][NPAIRS];
__device__ u64   g_fy[2][DD][NPAIRS];
__device__ float g_part[NSLOTS][NBLOCKS][2];
__device__ unsigned g_count;

__global__ void ode_init_kernel() { g_count = 0u; }

// ---- packed f32x2 helpers (sm_103a) ----
__device__ __forceinline__ u64 F2FMA(u64 a, u64 b, u64 c) {
    u64 d; asm("fma.rn.f32x2 %0,%1,%2,%3;" : "=l"(d) : "l"(a), "l"(b), "l"(c)); return d;
}
__device__ __forceinline__ u64 F2MUL(u64 a, u64 b) {
    u64 d; asm("mul.rn.f32x2 %0,%1,%2;" : "=l"(d) : "l"(a), "l"(b)); return d;
}
__device__ __forceinline__ u64 PACK2(float lo, float hi) {
    u64 d; asm("mov.b64 %0,{%1,%2};" : "=l"(d) : "f"(lo), "f"(hi)); return d;
}
__device__ __forceinline__ float2 UNPACK2(u64 v) {
    float2 r; asm("mov.b64 {%0,%1},%2;" : "=f"(r.x), "=f"(r.y) : "l"(v)); return r;
}
__device__ __forceinline__ u64 DUP(float s) { return PACK2(s, s); }

// hardware tanh (sm_75+): 1 MUFU op, max rel err ~2^-11
__device__ __forceinline__ float TANHA(float x) {
    float r; asm("tanh.approx.f32 %0,%1;" : "=f"(r) : "f"(x)); return r;
}
__device__ __forceinline__ u64 TANH2(u64 a) {
    float2 x = UNPACK2(a);
    return PACK2(TANHA(x.x), TANHA(x.y));
}

// ---- MLP: out = tanh(yin @ W1^T + b1) @ W2^T + b2 (packed, weights in smem) ----
// sW1 rows: 8 u64 per j = [w1*6 | b1 | pad].  sW2 rows: 6 u64 per j (W2[d][j] dup'd).
__device__ __forceinline__ void mlp(const u64* __restrict__ sW1, const u64* __restrict__ sW2,
                                    const u64* __restrict__ sb2,
                                    const u64 yin[DD], u64 out[DD]) {
    u64 o0=sb2[0],o1=sb2[1],o2=sb2[2],o3=sb2[3],o4=sb2[4],o5=sb2[5];
#pragma unroll 2
    for (int j = 0; j < HH; j++) {
        const ulonglong2* r = (const ulonglong2*)(sW1 + j*8);
        ulonglong2 wa = r[0], wb = r[1], wc = r[2], wd = r[3];
        u64 a = wd.x;                                   // b1[j]
        a = F2FMA(wa.x, yin[0], a); a = F2FMA(wa.y, yin[1], a);
        a = F2FMA(wb.x, yin[2], a); a = F2FMA(wb.y, yin[3], a);
        a = F2FMA(wc.x, yin[4], a); a = F2FMA(wc.y, yin[5], a);
        u64 t = TANH2(a);
        const ulonglong2* q = (const ulonglong2*)(sW2 + j*6);
        ulonglong2 va = q[0], vb = q[1], vc = q[2];
        o0 = F2FMA(va.x, t, o0); o1 = F2FMA(va.y, t, o1);
        o2 = F2FMA(vb.x, t, o2); o3 = F2FMA(vb.y, t, o3);
        o4 = F2FMA(vc.x, t, o4); o5 = F2FMA(vc.y, t, o5);
    }
    out[0]=o0; out[1]=o1; out[2]=o2; out[3]=o3; out[4]=o4; out[5]=o5;
}

__device__ __forceinline__ void axpy(u64 t[DD], const u64 k[DD], float c) {
    u64 cc = DUP(c);
#pragma unroll
    for (int d = 0; d < DD; d++) t[d] = F2FMA(cc, k[d], t[d]);
}

// ---- deterministic grid-wide sum of two floats; slot must increase per call ----
__device__ float2 reduce2(float a, float b, int slot) {
    __shared__ float swA[NTHREADS/32], swB[NTHREADS/32];
    __shared__ float2 bc;
    unsigned lane = threadIdx.x & 31, wid = threadIdx.x >> 5;
#pragma unroll
    for (int o = 16; o; o >>= 1) {
        a += __shfl_xor_sync(0xffffffffu, a, o);
        b += __shfl_xor_sync(0xffffffffu, b, o);
    }
    if (lane == 0) { swA[wid] = a; swB[wid] = b; }
    __syncthreads();
    if (threadIdx.x == 0) {
        float sa = 0.f, sb = 0.f;
#pragma unroll
        for (int i = 0; i < NTHREADS/32; i++) { sa += swA[i]; sb += swB[i]; }
        g_part[slot][blockIdx.x][0] = sa;
        g_part[slot][blockIdx.x][1] = sb;
        __threadfence();
        atomicAdd(&g_count, 1u);
        unsigned target = (unsigned)(slot + 1) * NBLOCKS;
        while (atomicAdd(&g_count, 0u) < target) __nanosleep(64);
        __threadfence();
        float ta = 0.f, tb = 0.f;
        for (int i = 0; i < NBLOCKS; i++) {
            ta += __ldcg(&g_part[slot][i][0]);
            tb += __ldcg(&g_part[slot][i][1]);
        }
        bc = make_float2(ta, tb);
    }
    __syncthreads();
    return bc;
}

__device__ __forceinline__ void err_acc(float& acc, u64 e, u64 yv, u64 yn) {
    float2 ef = UNPACK2(e), y0 = UNPACK2(yv), y1 = UNPACK2(yn);
    float s0 = fmaf(1e-7f, fmaxf(fabsf(y0.x), fabsf(y1.x)), 1e-9f);
    float s1 = fmaf(1e-7f, fmaxf(fabsf(y0.y), fabsf(y1.y)), 1e-9f);
    float q0 = __fdividef(ef.x, s0), q1 = __fdividef(ef.y, s1);
    acc = fmaf(q0, q0, acc); acc = fmaf(q1, q1, acc);
}

__global__ void __launch_bounds__(NTHREADS, 1)
ode_kernel(const float* __restrict__ in_seq, const float* __restrict__ W1,
           const float* __restrict__ b1, const float* __restrict__ W2,
           const float* __restrict__ b2, const float* __restrict__ Wl,
           const float* __restrict__ bl, float* __restrict__ out) {
    const float A21f = 0.2f;
    const float A31f = 3.f/40.f,  A32f = 9.f/40.f;
    const float A41f = 44.f/45.f, A42f = -56.f/15.f, A43f = 32.f/9.f;
    const float A51f = 19372.f/6561.f, A52f = -25360.f/2187.f, A53f = 64448.f/6561.f, A54f = -212.f/729.f;
    const float A61f = 9017.f/3168.f,  A62f = -355.f/33.f,     A63f = 46732.f/5247.f,
                A64f = 49.f/176.f,     A65f = -5103.f/18656.f;
    const float B1f = 35.f/384.f, B3f = 500.f/1113.f, B4f = 125.f/192.f, B5f = -2187.f/6784.f, B6f = 11.f/84.f;
    const float E1f = 71.f/57600.f, E3f = -71.f/16695.f, E4f = 71.f/1920.f,
                E5f = -17253.f/339200.f, E6f = 22.f/525.f, E7f = -1.f/40.f;
    const float INVN = 1.0f / (float)NELEM;

    __shared__ __align__(16) u64 sW1[HH*8];
    __shared__ __align__(16) u64 sW2[HH*6];
    __shared__ __align__(16) u64 sb2[DD];

    const int tid  = threadIdx.x;
    const int gtid = blockIdx.x * NTHREADS + tid;

    for (int i = tid; i < HH; i += NTHREADS) {
#pragma unroll
        for (int d = 0; d < DD; d++) {
            float w1v = W1[i*DD + d];   sW1[i*8 + d] = PACK2(w1v, w1v);
            float w2v = W2[d*HH + i];   sW2[i*6 + d] = PACK2(w2v, w2v);
        }
        float bv = b1[i];
        sW1[i*8 + 6] = PACK2(bv, bv);
        sW1[i*8 + 7] = 0ull;
    }
    if (tid < DD) { float v = b2[tid]; sb2[tid] = PACK2(v, v); }
    __syncthreads();

    int slot = 0;

    // ---- Pass A: y0 = input_seq[:,-1,:], f0 = f(y0), accumulate d0,d1 ----
    float a0 = 0.f, a1 = 0.f;
    for (int p = gtid; p < NPAIRS; p += TOTTHR) {
        const float* r0 = in_seq + (size_t)(2*p) * (TT*DD) + (TT-1)*DD;
        const float* r1 = r0 + TT*DD;
        u64 y[DD], f[DD];
#pragma unroll
        for (int d = 0; d < DD; d++) y[d] = PACK2(r0[d], r1[d]);
        mlp(sW1, sW2, sb2, y, f);
#pragma unroll
        for (int d = 0; d < DD; d++) {
            g_y[0][d][p]  = y[d];
            g_fy[0][d][p] = f[d];
            float2 yv = UNPACK2(y[d]), fv = UNPACK2(f[d]);
            float s0 = fmaf(1e-7f, fabsf(yv.x), 1e-9f);
            float s1 = fmaf(1e-7f, fabsf(yv.y), 1e-9f);
            float q0 = __fdividef(yv.x, s0), q1 = __fdividef(yv.y, s1);
            a0 = fmaf(q0, q0, a0); a0 = fmaf(q1, q1, a0);
            q0 = __fdividef(fv.x, s0); q1 = __fdividef(fv.y, s1);
            a1 = fmaf(q0, q0, a1); a1 = fmaf(q1, q1, a1);
        }
    }
    float2 s01 = reduce2(a0, a1, slot++);
    float d0 = sqrtf(s01.x * INVN), d1 = sqrtf(s01.y * INVN);
    float h0 = ((d0 < 1e-5f) || (d1 < 1e-5f)) ? 1e-6f : 0.01f * d0 / fmaxf(d1, 1e-12f);

    // ---- Pass B: d2 = rms((f(y0+h0*f0)-f0)/scale)/h0 ----
    float a2 = 0.f;
    for (int p = gtid; p < NPAIRS; p += TOTTHR) {
        u64 y[DD], f[DD], y1v[DD], f1v[DD];
#pragma unroll
        for (int d = 0; d < DD; d++) { y[d] = g_y[0][d][p]; f[d] = g_fy[0][d][p]; }
        u64 hh = DUP(h0);
#pragma unroll
        for (int d = 0; d < DD; d++) y1v[d] = F2FMA(hh, f[d], y[d]);
        mlp(sW1, sW2, sb2, y1v, f1v);
#pragma unroll
        for (int d = 0; d < DD; d++) {
            float2 yv = UNPACK2(y[d]), fv = UNPACK2(f[d]), gv = UNPACK2(f1v[d]);
            float s0 = fmaf(1e-7f, fabsf(yv.x), 1e-9f);
            float s1 = fmaf(1e-7f, fabsf(yv.y), 1e-9f);
            float q0 = __fdividef(gv.x - fv.x, s0), q1 = __fdividef(gv.y - fv.y, s1);
            a2 = fmaf(q0, q0, a2); a2 = fmaf(q1, q1, a2);
        }
    }
    float2 s2 = reduce2(a2, 0.f, slot++);
    float d2 = sqrtf(s2.x * INVN) / h0;
    float dm = fmaxf(d1, d2);
    float h1 = (dm <= 1e-15f) ? fmaxf(1e-6f, h0 * 1e-3f)
                              : powf(0.01f / fmaxf(dm, 1e-15f), 0.2f);
    float h = fminf(fminf(100.f * h0, h1), 1.0f);

    // ---- adaptive step loop with early exit ----
    float t = 0.f;
    int cur = 0;
    for (int it = 0; it < MAXSTEPS; it++) {
        if (t >= 1.0f - 1e-12f) break;
        float hc = fminf(h, 1.0f - t);
        float acc = 0.f;
        for (int p = gtid; p < NPAIRS; p += TOTTHR) {
            u64 y[DD], k1[DD], k2[DD], k3[DD], k4[DD], k5[DD];
            u64 tmp[DD], yp[DD], e[DD];
#pragma unroll
            for (int d = 0; d < DD; d++) { y[d] = g_y[cur][d][p]; k1[d] = g_fy[cur][d][p]; }
            // stage 2
#pragma unroll
            for (int d = 0; d < DD; d++) tmp[d] = y[d];
            axpy(tmp, k1, hc*A21f);
            mlp(sW1, sW2, sb2, tmp, k2);
            // stage 3
#pragma unroll
            for (int d = 0; d < DD; d++) tmp[d] = y[d];
            axpy(tmp, k1, hc*A31f); axpy(tmp, k2, hc*A32f);
            mlp(sW1, sW2, sb2, tmp, k3);
            // stage 4
#pragma unroll
            for (int d = 0; d < DD; d++) tmp[d] = y[d];
            axpy(tmp, k1, hc*A41f); axpy(tmp, k2, hc*A42f); axpy(tmp, k3, hc*A43f);
            mlp(sW1, sW2, sb2, tmp, k4);
            // stage 5 (peak live: y,k1,k2,k3,k4,tmp,k5 = 7 arrays)
#pragma unroll
            for (int d = 0; d < DD; d++) tmp[d] = y[d];
            axpy(tmp, k1, hc*A51f); axpy(tmp, k2, hc*A52f); axpy(tmp, k3, hc*A53f); axpy(tmp, k4, hc*A54f);
            mlp(sW1, sW2, sb2, tmp, k5);
            // stage-6 input (k2 dies here)
#pragma unroll
            for (int d = 0; d < DD; d++) tmp[d] = y[d];
            axpy(tmp, k1, hc*A61f); axpy(tmp, k2, hc*A62f); axpy(tmp, k3, hc*A63f);
            axpy(tmp, k4, hc*A64f); axpy(tmp, k5, hc*A65f);
            // partial y_new / err BEFORE stage-6 MLP (k1,k3,k4,k5 die here)
#pragma unroll
            for (int d = 0; d < DD; d++) yp[d] = y[d];
            axpy(yp, k1, hc*B1f); axpy(yp, k3, hc*B3f); axpy(yp, k4, hc*B4f); axpy(yp, k5, hc*B5f);
            {
                u64 c = DUP(hc*E1f);
#pragma unroll
                for (int d = 0; d < DD; d++) e[d] = F2MUL(c, k1[d]);
            }
            axpy(e, k3, hc*E3f); axpy(e, k4, hc*E4f); axpy(e, k5, hc*E5f);
            // stage 6 (live: y, tmp, yp, e, k6-out)
            mlp(sW1, sW2, sb2, tmp, k2);            // k2 register = k6
            axpy(yp, k2, hc*B6f);                    // y_new complete
            axpy(e,  k2, hc*E6f);
            // k7 = f(y_new); reuse k3 storage (live: y, yp, e, k7)
            mlp(sW1, sW2, sb2, yp, k3);
            axpy(e, k3, hc*E7f);
#pragma unroll
            for (int d = 0; d < DD; d++) {
                g_y [cur^1][d][p] = yp[d];
                g_fy[cur^1][d][p] = k3[d];
                err_acc(acc, e[d], y[d], yp[d]);
            }
        }
        float2 se = reduce2(acc, 0.f, slot++);
        float en = sqrtf(se.x * INVN);
        float pw = exp2f(-0.2f * log2f(fmaxf(en, 1e-10f)));
        float factor = fminf(fmaxf(0.9f * pw, 0.2f), 10.0f);
        if (en <= 1.0f) { t += hc; cur ^= 1; }
        h = hc * factor;
    }

    // ---- output: out[b] = dot(yT[b], Wl) + bl ----
    float wl0 = Wl[0], wl1 = Wl[1], wl2 = Wl[2], wl3 = Wl[3], wl4 = Wl[4], wl5 = Wl[5];
    float blv = bl[0];
    for (int p = gtid; p < NPAIRS; p += TOTTHR) {
        float o0 = blv, o1 = blv;
#pragma unroll
        for (int d = 0; d < DD; d++) {
            float2 yv = UNPACK2(g_y[cur][d][p]);
            float w = (d==0)?wl0:(d==1)?wl1:(d==2)?wl2:(d==3)?wl3:(d==4)?wl4:wl5;
            o0 = fmaf(yv.x, w, o0);
            o1 = fmaf(yv.y, w, o1);
        }
        out[2*p]   = o0;
        out[2*p+1] = o1;
    }
}

extern "C" void kernel_launch(void* const* d_in, const int* in_sizes, int n_in,
                              void* d_out, int out_size) {
    const float* in_seq = (const float*)d_in[0];
    const float* W1 = (const float*)d_in[1];
    const float* b1 = (const float*)d_in[2];
    const float* W2 = (const float*)d_in[3];
    const float* b2 = (const float*)d_in[4];
    const float* Wl = (const float*)d_in[5];
    const float* bl = (const float*)d_in[6];
    float* out = (float*)d_out;
    ode_init_kernel<<<1, 1>>>();
    ode_kernel<<<NBLOCKS, NTHREADS>>>(in_seq, W1, b1, W2, b2, Wl, bl, out);
}

// round 4
// speedup vs baseline: 1.3636x; 1.1269x over previous
#include <cuda_runtime.h>

typedef unsigned long long u64;

#define BATCH   262144
#define DD      6
#define HH      100
#define TT      8
#define NPAIRS  (BATCH/2)
#define NQUADS  (BATCH/4)
#define NELEM   (BATCH*DD)
#define NBLOCKS 148
#define NTHREADS 256
#define TOTTHR  (NBLOCKS*NTHREADS)
#define NSLOTS  72
#define MAXSTEPS 64

// ---- device scratch (no allocation allowed) ----
__device__ u64   g_y [2][DD][NPAIRS];
__device__ u64   g_fy[2][DD][NPAIRS];
__device__ float g_part[NSLOTS][NBLOCKS][2];
__device__ unsigned g_count;

__global__ void ode_init_kernel() { g_count = 0u; }

// ---- packed f32x2 helpers (sm_103a) ----
__device__ __forceinline__ u64 F2FMA(u64 a, u64 b, u64 c) {
    u64 d; asm("fma.rn.f32x2 %0,%1,%2,%3;" : "=l"(d) : "l"(a), "l"(b), "l"(c)); return d;
}
__device__ __forceinline__ u64 F2MUL(u64 a, u64 b) {
    u64 d; asm("mul.rn.f32x2 %0,%1,%2;" : "=l"(d) : "l"(a), "l"(b)); return d;
}
__device__ __forceinline__ u64 PACK2(float lo, float hi) {
    u64 d; asm("mov.b64 %0,{%1,%2};" : "=l"(d) : "f"(lo), "f"(hi)); return d;
}
__device__ __forceinline__ float2 UNPACK2(u64 v) {
    float2 r; asm("mov.b64 {%0,%1},%2;" : "=f"(r.x), "=f"(r.y) : "l"(v)); return r;
}
__device__ __forceinline__ u64 DUP(float s) { return PACK2(s, s); }

// hardware tanh (sm_75+): 1 MUFU op, max rel err ~2^-11
__device__ __forceinline__ float TANHA(float x) {
    float r; asm("tanh.approx.f32 %0,%1;" : "=f"(r) : "f"(x)); return r;
}
__device__ __forceinline__ u64 TANH2(u64 a) {
    float2 x = UNPACK2(a);
    return PACK2(TANHA(x.x), TANHA(x.y));
}

// ---- MLP on 4 rows (two packed pairs): amortizes weight LDS over 24 FMA2/j ----
// yin/out: [0..5] = pair A dims, [6..11] = pair B dims.
// sW1 rows: 8 u64 per j = [w1*6 | b1 | pad]. sW2 rows: 6 u64 per j.
__device__ __forceinline__ void mlp4(const u64* __restrict__ sW1, const u64* __restrict__ sW2,
                                     const u64* __restrict__ sb2,
                                     const u64 yin[12], u64 out[12]) {
#pragma unroll
    for (int d = 0; d < DD; d++) { out[d] = sb2[d]; out[d+6] = sb2[d]; }
#pragma unroll 1
    for (int j = 0; j < HH; j++) {
        const ulonglong2* r = (const ulonglong2*)(sW1 + j*8);
        ulonglong2 wa = r[0], wb = r[1], wc = r[2], wd = r[3];
        u64 aA = wd.x, aB = wd.x;                       // b1[j]
        aA = F2FMA(wa.x, yin[0], aA); aB = F2FMA(wa.x, yin[6],  aB);
        aA = F2FMA(wa.y, yin[1], aA); aB = F2FMA(wa.y, yin[7],  aB);
        aA = F2FMA(wb.x, yin[2], aA); aB = F2FMA(wb.x, yin[8],  aB);
        aA = F2FMA(wb.y, yin[3], aA); aB = F2FMA(wb.y, yin[9],  aB);
        aA = F2FMA(wc.x, yin[4], aA); aB = F2FMA(wc.x, yin[10], aB);
        aA = F2FMA(wc.y, yin[5], aA); aB = F2FMA(wc.y, yin[11], aB);
        u64 tA = TANH2(aA), tB = TANH2(aB);
        const ulonglong2* q = (const ulonglong2*)(sW2 + j*6);
        ulonglong2 va = q[0], vb = q[1], vc = q[2];
        out[0] = F2FMA(va.x, tA, out[0]); out[6]  = F2FMA(va.x, tB, out[6]);
        out[1] = F2FMA(va.y, tA, out[1]); out[7]  = F2FMA(va.y, tB, out[7]);
        out[2] = F2FMA(vb.x, tA, out[2]); out[8]  = F2FMA(vb.x, tB, out[8]);
        out[3] = F2FMA(vb.y, tA, out[3]); out[9]  = F2FMA(vb.y, tB, out[9]);
        out[4] = F2FMA(vc.x, tA, out[4]); out[10] = F2FMA(vc.x, tB, out[10]);
        out[5] = F2FMA(vc.y, tA, out[5]); out[11] = F2FMA(vc.y, tB, out[11]);
    }
}

__device__ __forceinline__ void axpy12(u64 t[12], const u64 k[12], float c) {
    u64 cc = DUP(c);
#pragma unroll
    for (int d = 0; d < 12; d++) t[d] = F2FMA(cc, k[d], t[d]);
}

// ---- deterministic grid-wide sum of two floats; slot must increase per call ----
__device__ float2 reduce2(float a, float b, int slot) {
    __shared__ float swA[NTHREADS/32], swB[NTHREADS/32];
    __shared__ float2 bc;
    unsigned lane = threadIdx.x & 31, wid = threadIdx.x >> 5;
#pragma unroll
    for (int o = 16; o; o >>= 1) {
        a += __shfl_xor_sync(0xffffffffu, a, o);
        b += __shfl_xor_sync(0xffffffffu, b, o);
    }
    if (lane == 0) { swA[wid] = a; swB[wid] = b; }
    __syncthreads();
    if (threadIdx.x == 0) {
        float sa = 0.f, sb = 0.f;
#pragma unroll
        for (int i = 0; i < NTHREADS/32; i++) { sa += swA[i]; sb += swB[i]; }
        g_part[slot][blockIdx.x][0] = sa;
        g_part[slot][blockIdx.x][1] = sb;
        __threadfence();
        atomicAdd(&g_count, 1u);
        unsigned target = (unsigned)(slot + 1) * NBLOCKS;
        while (atomicAdd(&g_count, 0u) < target) __nanosleep(64);
        __threadfence();
        float ta = 0.f, tb = 0.f;
        for (int i = 0; i < NBLOCKS; i++) {
            ta += __ldcg(&g_part[slot][i][0]);
            tb += __ldcg(&g_part[slot][i][1]);
        }
        bc = make_float2(ta, tb);
    }
    __syncthreads();
    return bc;
}

__device__ __forceinline__ void err_acc(float& acc, u64 e, u64 yv, u64 yn) {
    float2 ef = UNPACK2(e), y0 = UNPACK2(yv), y1 = UNPACK2(yn);
    float s0 = fmaf(1e-7f, fmaxf(fabsf(y0.x), fabsf(y1.x)), 1e-9f);
    float s1 = fmaf(1e-7f, fmaxf(fabsf(y0.y), fabsf(y1.y)), 1e-9f);
    float q0 = __fdividef(ef.x, s0), q1 = __fdividef(ef.y, s1);
    acc = fmaf(q0, q0, acc); acc = fmaf(q1, q1, acc);
}

__global__ void __launch_bounds__(NTHREADS)
ode_kernel(const float* __restrict__ in_seq, const float* __restrict__ W1,
           const float* __restrict__ b1, const float* __restrict__ W2,
           const float* __restrict__ b2, const float* __restrict__ Wl,
           const float* __restrict__ bl, float* __restrict__ out) {
    const float A21f = 0.2f;
    const float A31f = 3.f/40.f,  A32f = 9.f/40.f;
    const float A41f = 44.f/45.f, A42f = -56.f/15.f, A43f = 32.f/9.f;
    const float A51f = 19372.f/6561.f, A52f = -25360.f/2187.f, A53f = 64448.f/6561.f, A54f = -212.f/729.f;
    const float A61f = 9017.f/3168.f,  A62f = -355.f/33.f,     A63f = 46732.f/5247.f,
                A64f = 49.f/176.f,     A65f = -5103.f/18656.f;
    const float B1f = 35.f/384.f, B3f = 500.f/1113.f, B4f = 125.f/192.f, B5f = -2187.f/6784.f, B6f = 11.f/84.f;
    const float E1f = 71.f/57600.f, E3f = -71.f/16695.f, E4f = 71.f/1920.f,
                E5f = -17253.f/339200.f, E6f = 22.f/525.f, E7f = -1.f/40.f;
    const float INVN = 1.0f / (float)NELEM;

    __shared__ __align__(16) u64 sW1[HH*8];
    __shared__ __align__(16) u64 sW2[HH*6];
    __shared__ __align__(16) u64 sb2[DD];

    const int tid  = threadIdx.x;
    const int gtid = blockIdx.x * NTHREADS + tid;

    for (int i = tid; i < HH; i += NTHREADS) {
#pragma unroll
        for (int d = 0; d < DD; d++) {
            float w1v = W1[i*DD + d];   sW1[i*8 + d] = PACK2(w1v, w1v);
            float w2v = W2[d*HH + i];   sW2[i*6 + d] = PACK2(w2v, w2v);
        }
        float bv = b1[i];
        sW1[i*8 + 6] = PACK2(bv, bv);
        sW1[i*8 + 7] = 0ull;
    }
    if (tid < DD) { float v = b2[tid]; sb2[tid] = PACK2(v, v); }
    __syncthreads();

    int slot = 0;

    // ---- Pass A: y0 = input_seq[:,-1,:], f0 = f(y0), accumulate d0,d1 ----
    float a0 = 0.f, a1 = 0.f;
    for (int q = gtid; q < NQUADS; q += TOTTHR) {
        u64 y[12], f[12];
#pragma unroll
        for (int h = 0; h < 2; h++) {
            const float* r0 = in_seq + (size_t)(4*q + 2*h) * (TT*DD) + (TT-1)*DD;
            const float* r1 = r0 + TT*DD;
#pragma unroll
            for (int d = 0; d < DD; d++) y[6*h + d] = PACK2(r0[d], r1[d]);
        }
        mlp4(sW1, sW2, sb2, y, f);
#pragma unroll
        for (int h = 0; h < 2; h++) {
            int p = 2*q + h;
#pragma unroll
            for (int d = 0; d < DD; d++) {
                g_y[0][d][p]  = y[6*h + d];
                g_fy[0][d][p] = f[6*h + d];
                float2 yv = UNPACK2(y[6*h + d]), fv = UNPACK2(f[6*h + d]);
                float s0 = fmaf(1e-7f, fabsf(yv.x), 1e-9f);
                float s1 = fmaf(1e-7f, fabsf(yv.y), 1e-9f);
                float q0 = __fdividef(yv.x, s0), q1 = __fdividef(yv.y, s1);
                a0 = fmaf(q0, q0, a0); a0 = fmaf(q1, q1, a0);
                q0 = __fdividef(fv.x, s0); q1 = __fdividef(fv.y, s1);
                a1 = fmaf(q0, q0, a1); a1 = fmaf(q1, q1, a1);
            }
        }
    }
    float2 s01 = reduce2(a0, a1, slot++);
    float d0 = sqrtf(s01.x * INVN), d1 = sqrtf(s01.y * INVN);
    float h0 = ((d0 < 1e-5f) || (d1 < 1e-5f)) ? 1e-6f : 0.01f * d0 / fmaxf(d1, 1e-12f);

    // ---- Pass B: d2 = rms((f(y0+h0*f0)-f0)/scale)/h0 ----
    float a2 = 0.f;
    for (int q = gtid; q < NQUADS; q += TOTTHR) {
        u64 y[12], f[12], y1v[12], f1v[12];
#pragma unroll
        for (int h = 0; h < 2; h++) {
            int p = 2*q + h;
#pragma unroll
            for (int d = 0; d < DD; d++) { y[6*h+d] = g_y[0][d][p]; f[6*h+d] = g_fy[0][d][p]; }
        }
        u64 hh = DUP(h0);
#pragma unroll
        for (int d = 0; d < 12; d++) y1v[d] = F2FMA(hh, f[d], y[d]);
        mlp4(sW1, sW2, sb2, y1v, f1v);
#pragma unroll
        for (int d = 0; d < 12; d++) {
            float2 yv = UNPACK2(y[d]), fv = UNPACK2(f[d]), gv = UNPACK2(f1v[d]);
            float s0 = fmaf(1e-7f, fabsf(yv.x), 1e-9f);
            float s1 = fmaf(1e-7f, fabsf(yv.y), 1e-9f);
            float q0 = __fdividef(gv.x - fv.x, s0), q1 = __fdividef(gv.y - fv.y, s1);
            a2 = fmaf(q0, q0, a2); a2 = fmaf(q1, q1, a2);
        }
    }
    float2 s2 = reduce2(a2, 0.f, slot++);
    float d2 = sqrtf(s2.x * INVN) / h0;
    float dm = fmaxf(d1, d2);
    float h1 = (dm <= 1e-15f) ? fmaxf(1e-6f, h0 * 1e-3f)
                              : powf(0.01f / fmaxf(dm, 1e-15f), 0.2f);
    float h = fminf(fminf(100.f * h0, h1), 1.0f);

    // ---- adaptive step loop with early exit ----
    float t = 0.f;
    int cur = 0;
    for (int it = 0; it < MAXSTEPS; it++) {
        if (t >= 1.0f - 1e-12f) break;
        float hc = fminf(h, 1.0f - t);
        float acc = 0.f;
        for (int q = gtid; q < NQUADS; q += TOTTHR) {
            u64 y[12], k1[12], k2[12], k3[12], k4[12], k5[12];
            u64 tmp[12], yp[12], e[12];
#pragma unroll
            for (int h2 = 0; h2 < 2; h2++) {
                int p = 2*q + h2;
#pragma unroll
                for (int d = 0; d < DD; d++) { y[6*h2+d] = g_y[cur][d][p]; k1[6*h2+d] = g_fy[cur][d][p]; }
            }
            // stage 2
#pragma unroll
            for (int d = 0; d < 12; d++) tmp[d] = y[d];
            axpy12(tmp, k1, hc*A21f);
            mlp4(sW1, sW2, sb2, tmp, k2);
            // stage 3
#pragma unroll
            for (int d = 0; d < 12; d++) tmp[d] = y[d];
            axpy12(tmp, k1, hc*A31f); axpy12(tmp, k2, hc*A32f);
            mlp4(sW1, sW2, sb2, tmp, k3);
            // stage 4
#pragma unroll
            for (int d = 0; d < 12; d++) tmp[d] = y[d];
            axpy12(tmp, k1, hc*A41f); axpy12(tmp, k2, hc*A42f); axpy12(tmp, k3, hc*A43f);
            mlp4(sW1, sW2, sb2, tmp, k4);
            // stage 5
#pragma unroll
            for (int d = 0; d < 12; d++) tmp[d] = y[d];
            axpy12(tmp, k1, hc*A51f); axpy12(tmp, k2, hc*A52f); axpy12(tmp, k3, hc*A53f); axpy12(tmp, k4, hc*A54f);
            mlp4(sW1, sW2, sb2, tmp, k5);
            // stage-6 input (k2 dies here)
#pragma unroll
            for (int d = 0; d < 12; d++) tmp[d] = y[d];
            axpy12(tmp, k1, hc*A61f); axpy12(tmp, k2, hc*A62f); axpy12(tmp, k3, hc*A63f);
            axpy12(tmp, k4, hc*A64f); axpy12(tmp, k5, hc*A65f);
            // partial y_new / err BEFORE stage-6 MLP (k1,k3,k4,k5 die here)
#pragma unroll
            for (int d = 0; d < 12; d++) yp[d] = y[d];
            axpy12(yp, k1, hc*B1f); axpy12(yp, k3, hc*B3f); axpy12(yp, k4, hc*B4f); axpy12(yp, k5, hc*B5f);
            {
                u64 c = DUP(hc*E1f);
#pragma unroll
                for (int d = 0; d < 12; d++) e[d] = F2MUL(c, k1[d]);
            }
            axpy12(e, k3, hc*E3f); axpy12(e, k4, hc*E4f); axpy12(e, k5, hc*E5f);
            // stage 6
            mlp4(sW1, sW2, sb2, tmp, k2);            // k2 = k6
            axpy12(yp, k2, hc*B6f);                   // y_new complete
            axpy12(e,  k2, hc*E6f);
            // k7 = f(y_new)
            mlp4(sW1, sW2, sb2, yp, k3);              // k3 = k7
            axpy12(e, k3, hc*E7f);
#pragma unroll
            for (int h2 = 0; h2 < 2; h2++) {
                int p = 2*q + h2;
#pragma unroll
                for (int d = 0; d < DD; d++) {
                    g_y [cur^1][d][p] = yp[6*h2+d];
                    g_fy[cur^1][d][p] = k3[6*h2+d];
                    err_acc(acc, e[6*h2+d], y[6*h2+d], yp[6*h2+d]);
                }
            }
        }
        float2 se = reduce2(acc, 0.f, slot++);
        float en = sqrtf(se.x * INVN);
        float pw = exp2f(-0.2f * log2f(fmaxf(en, 1e-10f)));
        float factor = fminf(fmaxf(0.9f * pw, 0.2f), 10.0f);
        if (en <= 1.0f) { t += hc; cur ^= 1; }
        h = hc * factor;
    }

    // ---- output: out[b] = dot(yT[b], Wl) + bl ----
    float wl[DD];
#pragma unroll
    for (int d = 0; d < DD; d++) wl[d] = Wl[d];
    float blv = bl[0];
    for (int q = gtid; q < NQUADS; q += TOTTHR) {
#pragma unroll
        for (int h2 = 0; h2 < 2; h2++) {
            int p = 2*q + h2;
            float o0 = blv, o1 = blv;
#pragma unroll
            for (int d = 0; d < DD; d++) {
                float2 yv = UNPACK2(g_y[cur][d][p]);
                o0 = fmaf(yv.x, wl[d], o0);
                o1 = fmaf(yv.y, wl[d], o1);
            }
            out[2*p]   = o0;
            out[2*p+1] = o1;
        }
    }
}

extern "C" void kernel_launch(void* const* d_in, const int* in_sizes, int n_in,
                              void* d_out, int out_size) {
    const float* in_seq = (const float*)d_in[0];
    const float* W1 = (const float*)d_in[1];
    const float* b1 = (const float*)d_in[2];
    const float* W2 = (const float*)d_in[3];
    const float* b2 = (const float*)d_in[4];
    const float* Wl = (const float*)d_in[5];
    const float* bl = (const float*)d_in[6];
    float* out = (float*)d_out;
    ode_init_kernel<<<1, 1>>>();
    ode_kernel<<<NBLOCKS, NTHREADS>>>(in_seq, W1, b1, W2, b2, Wl, bl, out);
}

// round 5
// speedup vs baseline: 1.4699x; 1.0780x over previous
#include <cuda_runtime.h>

typedef unsigned long long u64;

#define BATCH   262144
#define DD      6
#define HH      100
#define TT      8
#define NPAIRS  (BATCH/2)
#define NQUADS  (BATCH/4)
#define NELEM   (BATCH*DD)
#define NBLOCKS 148
#define NTHREADS 256
#define TOTTHR  (NBLOCKS*NTHREADS)
#define NSLOTS  72
#define MAXSTEPS 64

// ---- device scratch (no allocation allowed) ----
__device__ u64   g_y [2][DD][NPAIRS];
__device__ u64   g_fy[2][DD][NPAIRS];
__device__ float g_part[NSLOTS][NBLOCKS][2];
__device__ unsigned g_count;

__global__ void ode_init_kernel() { g_count = 0u; }

// ---- packed f32x2 helpers (sm_103a) ----
__device__ __forceinline__ u64 F2FMA(u64 a, u64 b, u64 c) {
    u64 d; asm("fma.rn.f32x2 %0,%1,%2,%3;" : "=l"(d) : "l"(a), "l"(b), "l"(c)); return d;
}
__device__ __forceinline__ u64 F2MUL(u64 a, u64 b) {
    u64 d; asm("mul.rn.f32x2 %0,%1,%2;" : "=l"(d) : "l"(a), "l"(b)); return d;
}
__device__ __forceinline__ u64 PACK2(float lo, float hi) {
    u64 d; asm("mov.b64 %0,{%1,%2};" : "=l"(d) : "f"(lo), "f"(hi)); return d;
}
__device__ __forceinline__ float2 UNPACK2(u64 v) {
    float2 r; asm("mov.b64 {%0,%1},%2;" : "=f"(r.x), "=f"(r.y) : "l"(v)); return r;
}
__device__ __forceinline__ u64 DUP(float s) { return PACK2(s, s); }

// hardware tanh (sm_75+): 1 MUFU op
__device__ __forceinline__ float TANHA(float x) {
    float r; asm("tanh.approx.f32 %0,%1;" : "=f"(r) : "f"(x)); return r;
}
__device__ __forceinline__ u64 TANH2(u64 a) {
    float2 x = UNPACK2(a);
    return PACK2(TANHA(x.x), TANHA(x.y));
}

// ---- MLP on 4 rows (two packed pairs); j-loop unrolled x2 for ILP ----
// sW1 rows: 8 u64 per j = [w1*6 | b1 | pad]. sW2 rows: 6 u64 per j.
__device__ __forceinline__ void mlp4(const u64* __restrict__ sW1, const u64* __restrict__ sW2,
                                     const u64* __restrict__ sb2,
                                     const u64 yin[12], u64 out[12]) {
#pragma unroll
    for (int d = 0; d < DD; d++) { out[d] = sb2[d]; out[d+6] = sb2[d]; }
#pragma unroll 2
    for (int j = 0; j < HH; j++) {
        const ulonglong2* r = (const ulonglong2*)(sW1 + j*8);
        ulonglong2 wa = r[0], wb = r[1], wc = r[2], wd = r[3];
        u64 aA = wd.x, aB = wd.x;                       // b1[j]
        aA = F2FMA(wa.x, yin[0], aA); aB = F2FMA(wa.x, yin[6],  aB);
        aA = F2FMA(wa.y, yin[1], aA); aB = F2FMA(wa.y, yin[7],  aB);
        aA = F2FMA(wb.x, yin[2], aA); aB = F2FMA(wb.x, yin[8],  aB);
        aA = F2FMA(wb.y, yin[3], aA); aB = F2FMA(wb.y, yin[9],  aB);
        aA = F2FMA(wc.x, yin[4], aA); aB = F2FMA(wc.x, yin[10], aB);
        aA = F2FMA(wc.y, yin[5], aA); aB = F2FMA(wc.y, yin[11], aB);
        u64 tA = TANH2(aA), tB = TANH2(aB);
        const ulonglong2* q = (const ulonglong2*)(sW2 + j*6);
        ulonglong2 va = q[0], vb = q[1], vc = q[2];
        out[0] = F2FMA(va.x, tA, out[0]); out[6]  = F2FMA(va.x, tB, out[6]);
        out[1] = F2FMA(va.y, tA, out[1]); out[7]  = F2FMA(va.y, tB, out[7]);
        out[2] = F2FMA(vb.x, tA, out[2]); out[8]  = F2FMA(vb.x, tB, out[8]);
        out[3] = F2FMA(vb.y, tA, out[3]); out[9]  = F2FMA(vb.y, tB, out[9]);
        out[4] = F2FMA(vc.x, tA, out[4]); out[10] = F2FMA(vc.x, tB, out[10]);
        out[5] = F2FMA(vc.y, tA, out[5]); out[11] = F2FMA(vc.y, tB, out[11]);
    }
}

__device__ __forceinline__ void axpy12(u64 t[12], const u64 k[12], u64 cc) {
#pragma unroll
    for (int d = 0; d < 12; d++) t[d] = F2FMA(cc, k[d], t[d]);
}
// t = y + c*k (fused init, no copy)
__device__ __forceinline__ void setax12(u64 t[12], const u64 y[12], const u64 k[12], u64 cc) {
#pragma unroll
    for (int d = 0; d < 12; d++) t[d] = F2FMA(cc, k[d], y[d]);
}

// ---- deterministic grid-wide sum of two floats; slot must increase per call ----
__device__ float2 reduce2(float a, float b, int slot) {
    __shared__ float swA[NTHREADS/32], swB[NTHREADS/32];
    __shared__ float2 bc;
    unsigned lane = threadIdx.x & 31, wid = threadIdx.x >> 5;
#pragma unroll
    for (int o = 16; o; o >>= 1) {
        a += __shfl_xor_sync(0xffffffffu, a, o);
        b += __shfl_xor_sync(0xffffffffu, b, o);
    }
    if (lane == 0) { swA[wid] = a; swB[wid] = b; }
    __syncthreads();
    if (threadIdx.x == 0) {
        float sa = 0.f, sb = 0.f;
#pragma unroll
        for (int i = 0; i < NTHREADS/32; i++) { sa += swA[i]; sb += swB[i]; }
        g_part[slot][blockIdx.x][0] = sa;
        g_part[slot][blockIdx.x][1] = sb;
        __threadfence();
        atomicAdd(&g_count, 1u);
        unsigned target = (unsigned)(slot + 1) * NBLOCKS;
        while (atomicAdd(&g_count, 0u) < target) __nanosleep(64);
        __threadfence();
        float ta = 0.f, tb = 0.f;
        for (int i = 0; i < NBLOCKS; i++) {
            ta += __ldcg(&g_part[slot][i][0]);
            tb += __ldcg(&g_part[slot][i][1]);
        }
        bc = make_float2(ta, tb);
    }
    __syncthreads();
    return bc;
}

__device__ __forceinline__ void err_acc(float& acc, u64 e, u64 yv, u64 yn) {
    float2 ef = UNPACK2(e), y0 = UNPACK2(yv), y1 = UNPACK2(yn);
    float s0 = fmaf(1e-7f, fmaxf(fabsf(y0.x), fabsf(y1.x)), 1e-9f);
    float s1 = fmaf(1e-7f, fmaxf(fabsf(y0.y), fabsf(y1.y)), 1e-9f);
    float q0 = __fdividef(ef.x, s0), q1 = __fdividef(ef.y, s1);
    acc = fmaf(q0, q0, acc); acc = fmaf(q1, q1, acc);
}

__global__ void __launch_bounds__(NTHREADS)
ode_kernel(const float* __restrict__ in_seq, const float* __restrict__ W1,
           const float* __restrict__ b1, const float* __restrict__ W2,
           const float* __restrict__ b2, const float* __restrict__ Wl,
           const float* __restrict__ bl, float* __restrict__ out) {
    const float A21f = 0.2f;
    const float A31f = 3.f/40.f,  A32f = 9.f/40.f;
    const float A41f = 44.f/45.f, A42f = -56.f/15.f, A43f = 32.f/9.f;
    const float A51f = 19372.f/6561.f, A52f = -25360.f/2187.f, A53f = 64448.f/6561.f, A54f = -212.f/729.f;
    const float A61f = 9017.f/3168.f,  A62f = -355.f/33.f,     A63f = 46732.f/5247.f,
                A64f = 49.f/176.f,     A65f = -5103.f/18656.f;
    const float B1f = 35.f/384.f, B3f = 500.f/1113.f, B4f = 125.f/192.f, B5f = -2187.f/6784.f, B6f = 11.f/84.f;
    const float E1f = 71.f/57600.f, E3f = -71.f/16695.f, E4f = 71.f/1920.f,
                E5f = -17253.f/339200.f, E6f = 22.f/525.f, E7f = -1.f/40.f;
    const float INVN = 1.0f / (float)NELEM;

    __shared__ __align__(16) u64 sW1[HH*8];
    __shared__ __align__(16) u64 sW2[HH*6];
    __shared__ __align__(16) u64 sb2[DD];

    const int tid  = threadIdx.x;
    const int gtid = blockIdx.x * NTHREADS + tid;

    for (int i = tid; i < HH; i += NTHREADS) {
#pragma unroll
        for (int d = 0; d < DD; d++) {
            float w1v = W1[i*DD + d];   sW1[i*8 + d] = PACK2(w1v, w1v);
            float w2v = W2[d*HH + i];   sW2[i*6 + d] = PACK2(w2v, w2v);
        }
        float bv = b1[i];
        sW1[i*8 + 6] = PACK2(bv, bv);
        sW1[i*8 + 7] = 0ull;
    }
    if (tid < DD) { float v = b2[tid]; sb2[tid] = PACK2(v, v); }
    __syncthreads();

    int slot = 0;

    // ---- Pass A: y0 = input_seq[:,-1,:], f0 = f(y0), accumulate d0,d1 ----
    float a0 = 0.f, a1 = 0.f;
    for (int q = gtid; q < NQUADS; q += TOTTHR) {
        u64 y[12], f[12];
#pragma unroll
        for (int h = 0; h < 2; h++) {
            const float* r0 = in_seq + (size_t)(4*q + 2*h) * (TT*DD) + (TT-1)*DD;
            const float* r1 = r0 + TT*DD;
#pragma unroll
            for (int d = 0; d < DD; d++) y[6*h + d] = PACK2(r0[d], r1[d]);
        }
        mlp4(sW1, sW2, sb2, y, f);
#pragma unroll
        for (int h = 0; h < 2; h++) {
            int p = 2*q + h;
#pragma unroll
            for (int d = 0; d < DD; d++) {
                g_y[0][d][p]  = y[6*h + d];
                g_fy[0][d][p] = f[6*h + d];
                float2 yv = UNPACK2(y[6*h + d]), fv = UNPACK2(f[6*h + d]);
                float s0 = fmaf(1e-7f, fabsf(yv.x), 1e-9f);
                float s1 = fmaf(1e-7f, fabsf(yv.y), 1e-9f);
                float q0 = __fdividef(yv.x, s0), q1 = __fdividef(yv.y, s1);
                a0 = fmaf(q0, q0, a0); a0 = fmaf(q1, q1, a0);
                q0 = __fdividef(fv.x, s0); q1 = __fdividef(fv.y, s1);
                a1 = fmaf(q0, q0, a1); a1 = fmaf(q1, q1, a1);
            }
        }
    }
    float2 s01 = reduce2(a0, a1, slot++);
    float d0 = sqrtf(s01.x * INVN), d1 = sqrtf(s01.y * INVN);
    float h0 = ((d0 < 1e-5f) || (d1 < 1e-5f)) ? 1e-6f : 0.01f * d0 / fmaxf(d1, 1e-12f);

    // ---- Pass B: d2 = rms((f(y0+h0*f0)-f0)/scale)/h0 ----
    float a2 = 0.f;
    for (int q = gtid; q < NQUADS; q += TOTTHR) {
        u64 y[12], f[12], y1v[12], f1v[12];
#pragma unroll
        for (int h = 0; h < 2; h++) {
            int p = 2*q + h;
#pragma unroll
            for (int d = 0; d < DD; d++) { y[6*h+d] = g_y[0][d][p]; f[6*h+d] = g_fy[0][d][p]; }
        }
        u64 hh = DUP(h0);
        setax12(y1v, y, f, hh);
        mlp4(sW1, sW2, sb2, y1v, f1v);
#pragma unroll
        for (int d = 0; d < 12; d++) {
            float2 yv = UNPACK2(y[d]), fv = UNPACK2(f[d]), gv = UNPACK2(f1v[d]);
            float s0 = fmaf(1e-7f, fabsf(yv.x), 1e-9f);
            float s1 = fmaf(1e-7f, fabsf(yv.y), 1e-9f);
            float q0 = __fdividef(gv.x - fv.x, s0), q1 = __fdividef(gv.y - fv.y, s1);
            a2 = fmaf(q0, q0, a2); a2 = fmaf(q1, q1, a2);
        }
    }
    float2 s2 = reduce2(a2, 0.f, slot++);
    float d2 = sqrtf(s2.x * INVN) / h0;
    float dm = fmaxf(d1, d2);
    float h1 = (dm <= 1e-15f) ? fmaxf(1e-6f, h0 * 1e-3f)
                              : powf(0.01f / fmaxf(dm, 1e-15f), 0.2f);
    float h = fminf(fminf(100.f * h0, h1), 1.0f);

    // ---- adaptive step loop with early exit ----
    float t = 0.f;
    int cur = 0;
    for (int it = 0; it < MAXSTEPS; it++) {
        if (t >= 1.0f - 1e-12f) break;
        float hc = fminf(h, 1.0f - t);
        // hoisted stage coefficients (packed)
        u64 c21 = DUP(hc*A21f);
        u64 c31 = DUP(hc*A31f), c32 = DUP(hc*A32f);
        u64 c41 = DUP(hc*A41f), c42 = DUP(hc*A42f), c43 = DUP(hc*A43f);
        u64 c51 = DUP(hc*A51f), c52 = DUP(hc*A52f), c53 = DUP(hc*A53f), c54 = DUP(hc*A54f);
        u64 c61 = DUP(hc*A61f), c62 = DUP(hc*A62f), c63 = DUP(hc*A63f), c64 = DUP(hc*A64f), c65 = DUP(hc*A65f);
        u64 cb1 = DUP(hc*B1f), cb3 = DUP(hc*B3f), cb4 = DUP(hc*B4f), cb5 = DUP(hc*B5f), cb6 = DUP(hc*B6f);
        u64 ce1 = DUP(hc*E1f), ce3 = DUP(hc*E3f), ce4 = DUP(hc*E4f), ce5 = DUP(hc*E5f),
            ce6 = DUP(hc*E6f), ce7 = DUP(hc*E7f);
        float acc = 0.f;
        for (int q = gtid; q < NQUADS; q += TOTTHR) {
            u64 y[12], k1[12], k2[12], k3[12], k4[12], k5[12];
            u64 tmp[12], yp[12], e[12];
#pragma unroll
            for (int h2 = 0; h2 < 2; h2++) {
                int p = 2*q + h2;
#pragma unroll
                for (int d = 0; d < DD; d++) { y[6*h2+d] = g_y[cur][d][p]; k1[6*h2+d] = g_fy[cur][d][p]; }
            }
            // stage 2
            setax12(tmp, y, k1, c21);
            mlp4(sW1, sW2, sb2, tmp, k2);
            // stage 3
            setax12(tmp, y, k1, c31); axpy12(tmp, k2, c32);
            mlp4(sW1, sW2, sb2, tmp, k3);
            // stage 4
            setax12(tmp, y, k1, c41); axpy12(tmp, k2, c42); axpy12(tmp, k3, c43);
            mlp4(sW1, sW2, sb2, tmp, k4);
            // stage 5
            setax12(tmp, y, k1, c51); axpy12(tmp, k2, c52); axpy12(tmp, k3, c53); axpy12(tmp, k4, c54);
            mlp4(sW1, sW2, sb2, tmp, k5);
            // stage-6 input (k2 dies here)
            setax12(tmp, y, k1, c61); axpy12(tmp, k2, c62); axpy12(tmp, k3, c63);
            axpy12(tmp, k4, c64); axpy12(tmp, k5, c65);
            // partial y_new / err BEFORE stage-6 MLP (k1,k3,k4,k5 die here)
            setax12(yp, y, k1, cb1); axpy12(yp, k3, cb3); axpy12(yp, k4, cb4); axpy12(yp, k5, cb5);
#pragma unroll
            for (int d = 0; d < 12; d++) e[d] = F2MUL(ce1, k1[d]);
            axpy12(e, k3, ce3); axpy12(e, k4, ce4); axpy12(e, k5, ce5);
            // stage 6
            mlp4(sW1, sW2, sb2, tmp, k2);            // k2 = k6
            axpy12(yp, k2, cb6);                      // y_new complete
            axpy12(e,  k2, ce6);
            // k7 = f(y_new)
            mlp4(sW1, sW2, sb2, yp, k3);              // k3 = k7
            axpy12(e, k3, ce7);
#pragma unroll
            for (int h2 = 0; h2 < 2; h2++) {
                int p = 2*q + h2;
#pragma unroll
                for (int d = 0; d < DD; d++) {
                    g_y [cur^1][d][p] = yp[6*h2+d];
                    g_fy[cur^1][d][p] = k3[6*h2+d];
                    err_acc(acc, e[6*h2+d], y[6*h2+d], yp[6*h2+d]);
                }
            }
        }
        float2 se = reduce2(acc, 0.f, slot++);
        float en = sqrtf(se.x * INVN);
        float pw = exp2f(-0.2f * log2f(fmaxf(en, 1e-10f)));
        float factor = fminf(fmaxf(0.9f * pw, 0.2f), 10.0f);
        if (en <= 1.0f) { t += hc; cur ^= 1; }
        h = hc * factor;
    }

    // ---- output: out[b] = dot(yT[b], Wl) + bl ----
    float wl[DD];
#pragma unroll
    for (int d = 0; d < DD; d++) wl[d] = Wl[d];
    float blv = bl[0];
    for (int q = gtid; q < NQUADS; q += TOTTHR) {
#pragma unroll
        for (int h2 = 0; h2 < 2; h2++) {
            int p = 2*q + h2;
            float o0 = blv, o1 = blv;
#pragma unroll
            for (int d = 0; d < DD; d++) {
                float2 yv = UNPACK2(g_y[cur][d][p]);
                o0 = fmaf(yv.x, wl[d], o0);
                o1 = fmaf(yv.y, wl[d], o1);
            }
            out[2*p]   = o0;
            out[2*p+1] = o1;
        }
    }
}

extern "C" void kernel_launch(void* const* d_in, const int* in_sizes, int n_in,
                              void* d_out, int out_size) {
    const float* in_seq = (const float*)d_in[0];
    const float* W1 = (const float*)d_in[1];
    const float* b1 = (const float*)d_in[2];
    const float* W2 = (const float*)d_in[3];
    const float* b2 = (const float*)d_in[4];
    const float* Wl = (const float*)d_in[5];
    const float* bl = (const float*)d_in[6];
    float* out = (float*)d_out;
    ode_init_kernel<<<1, 1>>>();
    ode_kernel<<<NBLOCKS, NTHREADS>>>(in_seq, W1, b1, W2, b2, Wl, bl, out);
}